// round 7
// baseline (speedup 1.0000x reference)
#include <cuda_runtime.h>
#include <math.h>

#define BB 8
#define NN 1024
#define EE 768
#define HH 12
#define HD 64
#define GK 768

// Scratch (device globals: allocation-free per harness rules)
__device__ float g_q[(size_t)BB*HH*NN*HD];     // [B,H,N,64]
__device__ float g_k[(size_t)BB*HH*NN*HD];
__device__ float g_v[(size_t)BB*HH*NN*HD];
__device__ float g_ctx[(size_t)BB*NN*EE];      // [B*N, 768]

__device__ __forceinline__ unsigned f2tf(float x){
    unsigned r; asm("cvt.rna.tf32.f32 %0, %1;" : "=r"(r) : "f"(x)); return r;
}
__device__ __forceinline__ float f2tf_f(float x){ return __uint_as_float(f2tf(x)); }

__device__ __forceinline__ void mma8(float* c, const unsigned* a, const unsigned* b){
    asm volatile("mma.sync.aligned.m16n8k8.row.col.f32.tf32.tf32.f32 "
        "{%0,%1,%2,%3}, {%4,%5,%6,%7}, {%8,%9}, {%0,%1,%2,%3};\n"
        : "+f"(c[0]),"+f"(c[1]),"+f"(c[2]),"+f"(c[3])
        : "r"(a[0]),"r"(a[1]),"r"(a[2]),"r"(a[3]), "r"(b[0]),"r"(b[1]));
}

// ---------------------------------------------------------------------------
// NT GEMM: C[M,Ncols] = A[M,768] @ W[Ncols,768]^T + bias
// MODE 0: A = query, Ncols=2304, epilogue scatters into g_q/g_k/g_v [B,H,N,64]
// MODE 1: A = g_ctx, Ncols=768,  epilogue writes Cout row-major + bias
// Block tile 128x128x32, 256 threads (8 warps, 2x4), warp tile 64x32,
// mma m16n8k8 tf32. smem stride 133 -> conflict-free STS, <=2-way LDS.
// ---------------------------------------------------------------------------
template<int MODE>
__global__ void __launch_bounds__(256) gemm_k(
    const float* __restrict__ Ain, const float* __restrict__ Bw,
    const float* __restrict__ bias, float* __restrict__ Cout)
{
    __shared__ float As[32][133];
    __shared__ float Bs[32][133];
    const float* A = (MODE == 0) ? Ain : g_ctx;

    const int t = threadIdx.x;
    const int lane = t & 31, wid = t >> 5;
    const int group = lane >> 2, tig = lane & 3;
    const int wm = wid >> 2, wn = wid & 3;
    const int m0 = blockIdx.y * 128, n0 = blockIdx.x * 128;
    const int rw = t >> 3;            // 0..31 tile row for loading
    const int c4 = (t & 7) * 4;       // k-offset within 32

    const float* ag = A  + (size_t)(m0 + rw) * GK + c4;
    const float* bg = Bw + (size_t)(n0 + rw) * GK + c4;

    float4 pa[4], pb[4];
#pragma unroll
    for (int i = 0; i < 4; i++) {
        pa[i] = *(const float4*)(ag + (size_t)i * 32 * GK);
        pb[i] = *(const float4*)(bg + (size_t)i * 32 * GK);
    }

    float acc[4][4][4];
#pragma unroll
    for (int mi = 0; mi < 4; mi++)
#pragma unroll
        for (int ni = 0; ni < 4; ni++)
#pragma unroll
            for (int v = 0; v < 4; v++) acc[mi][ni][v] = 0.f;

    const int KT = GK / 32;  // 24
#pragma unroll 1
    for (int kt = 0; kt < KT; kt++) {
        // stage current tile regs -> smem (tf32-converted)
#pragma unroll
        for (int i = 0; i < 4; i++) {
            As[c4+0][rw+32*i] = f2tf_f(pa[i].x);
            As[c4+1][rw+32*i] = f2tf_f(pa[i].y);
            As[c4+2][rw+32*i] = f2tf_f(pa[i].z);
            As[c4+3][rw+32*i] = f2tf_f(pa[i].w);
            Bs[c4+0][rw+32*i] = f2tf_f(pb[i].x);
            Bs[c4+1][rw+32*i] = f2tf_f(pb[i].y);
            Bs[c4+2][rw+32*i] = f2tf_f(pb[i].z);
            Bs[c4+3][rw+32*i] = f2tf_f(pb[i].w);
        }
        __syncthreads();
        // prefetch next tile (LDG in flight during compute)
        if (kt + 1 < KT) {
            const float* ag2 = ag + (kt + 1) * 32;
            const float* bg2 = bg + (kt + 1) * 32;
#pragma unroll
            for (int i = 0; i < 4; i++) {
                pa[i] = *(const float4*)(ag2 + (size_t)i * 32 * GK);
                pb[i] = *(const float4*)(bg2 + (size_t)i * 32 * GK);
            }
        }
        // compute 128x128x32
#pragma unroll
        for (int ks = 0; ks < 4; ks++) {
            const int kb = ks * 8;
            unsigned af[4][4], bf[4][2];
#pragma unroll
            for (int mi = 0; mi < 4; mi++) {
                const int mm = wm * 64 + mi * 16 + group;
                af[mi][0] = __float_as_uint(As[kb+tig  ][mm  ]);
                af[mi][1] = __float_as_uint(As[kb+tig  ][mm+8]);
                af[mi][2] = __float_as_uint(As[kb+tig+4][mm  ]);
                af[mi][3] = __float_as_uint(As[kb+tig+4][mm+8]);
            }
#pragma unroll
            for (int ni = 0; ni < 4; ni++) {
                const int nn2 = wn * 32 + ni * 8 + group;
                bf[ni][0] = __float_as_uint(Bs[kb+tig  ][nn2]);
                bf[ni][1] = __float_as_uint(Bs[kb+tig+4][nn2]);
            }
#pragma unroll
            for (int mi = 0; mi < 4; mi++)
#pragma unroll
                for (int ni = 0; ni < 4; ni++)
                    mma8(acc[mi][ni], af[mi], bf[ni]);
        }
        __syncthreads();
    }

    // epilogue
    float bv0[4], bv1[4];
#pragma unroll
    for (int ni = 0; ni < 4; ni++) {
        const int c = n0 + wn * 32 + ni * 8 + 2 * tig;
        bv0[ni] = bias[c]; bv1[ni] = bias[c + 1];
    }

    if (MODE == 0) {
        const int which = blockIdx.x / 6;   // 0=q 1=k 2=v (768 = 6 * 128)
        float* dstbuf = (which == 0) ? g_q : ((which == 1) ? g_k : g_v);
#pragma unroll
        for (int mi = 0; mi < 4; mi++)
#pragma unroll
            for (int rr = 0; rr < 2; rr++) {
                const int r  = m0 + wm * 64 + mi * 16 + group + rr * 8;
                const int bi = r >> 10, nidx = r & 1023;
#pragma unroll
                for (int ni = 0; ni < 4; ni++) {
                    const int c = n0 + wn * 32 + ni * 8 + 2 * tig;
                    const int e = c - which * 768;
                    const int h = e >> 6, d = e & 63;
                    float2 val;
                    val.x = acc[mi][ni][rr*2+0] + bv0[ni];
                    val.y = acc[mi][ni][rr*2+1] + bv1[ni];
                    *(float2*)&dstbuf[(((size_t)bi * HH + h) * NN + nidx) * HD + d] = val;
                }
            }
    } else {
#pragma unroll
        for (int mi = 0; mi < 4; mi++)
#pragma unroll
            for (int rr = 0; rr < 2; rr++) {
                const int r = m0 + wm * 64 + mi * 16 + group + rr * 8;
#pragma unroll
                for (int ni = 0; ni < 4; ni++) {
                    const int c = n0 + wn * 32 + ni * 8 + 2 * tig;
                    float2 val;
                    val.x = acc[mi][ni][rr*2+0] + bv0[ni];
                    val.y = acc[mi][ni][rr*2+1] + bv1[ni];
                    *(float2*)&Cout[(size_t)r * EE + c] = val;
                }
            }
    }
}

// ---------------------------------------------------------------------------
// Flash attention: grid (16 q-tiles, 96 bh), 128 threads (4 warps x 16 rows).
// Q tile [64,64] scaled+tf32 in smem (transposed [d][m]).
// Loop 16 key-tiles of 64: S = Q K^T (tf32 mma), online softmax in regs,
// P staged through smem transposed [key][m], O += P V (tf32 mma).
// smem stride 72 -> A/Vs fragment loads conflict-free, Ks 2-way.
// ---------------------------------------------------------------------------
__global__ void __launch_bounds__(128) attn_k()
{
    extern __shared__ float sm[];
    float* Qs = sm;                 // [64][72] stored [d][m]
    float* Ks = sm + 64 * 72;       // [key][d]
    float* Vs = sm + 2 * 64 * 72;   // [key][d]
    float* Ps = sm + 3 * 64 * 72;   // [key][m]

    const int t = threadIdx.x, lane = t & 31, wid = t >> 5;
    const int group = lane >> 2, tig = lane & 3;
    const int mstrip = wid * 16;
    const int bh = blockIdx.y, qt = blockIdx.x;

    {   // load Q tile, pre-scale by 1/sqrt(64), convert to tf32, transpose
        const size_t baseQ = ((size_t)bh * NN + qt * 64) * HD;
#pragma unroll
        for (int i = 0; i < 8; i++) {
            const int idx = t + i * 128;
            const int row = idx >> 4, d4 = (idx & 15) * 4;
            float4 v = *(const float4*)&g_q[baseQ + row * 64 + d4];
            Qs[(d4+0)*72 + row] = f2tf_f(v.x * 0.125f);
            Qs[(d4+1)*72 + row] = f2tf_f(v.y * 0.125f);
            Qs[(d4+2)*72 + row] = f2tf_f(v.z * 0.125f);
            Qs[(d4+3)*72 + row] = f2tf_f(v.w * 0.125f);
        }
    }

    float oc[8][4];
#pragma unroll
    for (int ni = 0; ni < 8; ni++)
#pragma unroll
        for (int v = 0; v < 4; v++) oc[ni][v] = 0.f;
    float mprev[2] = {-1e30f, -1e30f};
    float lsum[2]  = {0.f, 0.f};

#pragma unroll 1
    for (int kt = 0; kt < 16; kt++) {
        __syncthreads();   // prev iter done with Ks/Vs; Qs visible on kt=0
        {
            const size_t baseK = ((size_t)bh * NN + kt * 64) * HD;
#pragma unroll
            for (int i = 0; i < 8; i++) {
                const int idx = t + i * 128;
                const int row = idx >> 4, d4 = (idx & 15) * 4;
                float4 kv = *(const float4*)&g_k[baseK + row * 64 + d4];
                float4 vv = *(const float4*)&g_v[baseK + row * 64 + d4];
                float4 kc = make_float4(f2tf_f(kv.x), f2tf_f(kv.y), f2tf_f(kv.z), f2tf_f(kv.w));
                float4 vc = make_float4(f2tf_f(vv.x), f2tf_f(vv.y), f2tf_f(vv.z), f2tf_f(vv.w));
                *(float4*)&Ks[row * 72 + d4] = kc;
                *(float4*)&Vs[row * 72 + d4] = vc;
            }
        }
        __syncthreads();

        // S = Q K^T  (per warp: 16 rows x 64 keys)
        float sc[8][4];
#pragma unroll
        for (int ni = 0; ni < 8; ni++)
#pragma unroll
            for (int v = 0; v < 4; v++) sc[ni][v] = 0.f;
#pragma unroll
        for (int ks = 0; ks < 8; ks++) {
            const int kb = ks * 8;
            unsigned a[4];
            a[0] = __float_as_uint(Qs[(kb+tig  )*72 + mstrip + group    ]);
            a[1] = __float_as_uint(Qs[(kb+tig  )*72 + mstrip + group + 8]);
            a[2] = __float_as_uint(Qs[(kb+tig+4)*72 + mstrip + group    ]);
            a[3] = __float_as_uint(Qs[(kb+tig+4)*72 + mstrip + group + 8]);
#pragma unroll
            for (int ni = 0; ni < 8; ni++) {
                unsigned b[2];
                b[0] = __float_as_uint(Ks[(ni*8+group)*72 + kb+tig  ]);
                b[1] = __float_as_uint(Ks[(ni*8+group)*72 + kb+tig+4]);
                mma8(sc[ni], a, b);
            }
        }

        // online softmax (rows group and group+8; stats over lane-quad)
#pragma unroll
        for (int rr = 0; rr < 2; rr++) {
            float tm = -1e30f;
#pragma unroll
            for (int ni = 0; ni < 8; ni++)
                tm = fmaxf(tm, fmaxf(sc[ni][rr*2], sc[ni][rr*2+1]));
            tm = fmaxf(tm, __shfl_xor_sync(0xffffffffu, tm, 1));
            tm = fmaxf(tm, __shfl_xor_sync(0xffffffffu, tm, 2));
            const float mnew = fmaxf(mprev[rr], tm);
            const float corr = __expf(mprev[rr] - mnew);
            mprev[rr] = mnew;
            float rs = 0.f;
#pragma unroll
            for (int ni = 0; ni < 8; ni++) {
                const float p0 = __expf(sc[ni][rr*2]   - mnew);
                const float p1 = __expf(sc[ni][rr*2+1] - mnew);
                sc[ni][rr*2] = p0; sc[ni][rr*2+1] = p1;
                rs += p0 + p1;
            }
            rs += __shfl_xor_sync(0xffffffffu, rs, 1);
            rs += __shfl_xor_sync(0xffffffffu, rs, 2);
            lsum[rr] = lsum[rr] * corr + rs;
#pragma unroll
            for (int ni = 0; ni < 8; ni++) {
                oc[ni][rr*2]   *= corr;
                oc[ni][rr*2+1] *= corr;
            }
        }

        // stage P transposed [key][m] (per-warp disjoint m columns)
#pragma unroll
        for (int ni = 0; ni < 8; ni++) {
            const int c0 = ni * 8 + 2 * tig;
            const int r0 = mstrip + group;
            Ps[(c0  )*72 + r0  ] = f2tf_f(sc[ni][0]);
            Ps[(c0+1)*72 + r0  ] = f2tf_f(sc[ni][1]);
            Ps[(c0  )*72 + r0+8] = f2tf_f(sc[ni][2]);
            Ps[(c0+1)*72 + r0+8] = f2tf_f(sc[ni][3]);
        }
        __syncwarp();

        // O += P V
#pragma unroll
        for (int ks = 0; ks < 8; ks++) {
            const int kb = ks * 8;
            unsigned a[4];
            a[0] = __float_as_uint(Ps[(kb+tig  )*72 + mstrip + group    ]);
            a[1] = __float_as_uint(Ps[(kb+tig  )*72 + mstrip + group + 8]);
            a[2] = __float_as_uint(Ps[(kb+tig+4)*72 + mstrip + group    ]);
            a[3] = __float_as_uint(Ps[(kb+tig+4)*72 + mstrip + group + 8]);
#pragma unroll
            for (int ni = 0; ni < 8; ni++) {
                unsigned b[2];
                b[0] = __float_as_uint(Vs[(kb+tig  )*72 + ni*8+group]);
                b[1] = __float_as_uint(Vs[(kb+tig+4)*72 + ni*8+group]);
                mma8(oc[ni], a, b);
            }
        }
    }

    // normalize + write ctx [B*N, 768] at column h*64
    const int bi = bh / HH, h = bh % HH;
#pragma unroll
    for (int rr = 0; rr < 2; rr++) {
        const float inv = 1.0f / lsum[rr];
        const int q = qt * 64 + mstrip + group + rr * 8;
        const size_t rowoff = ((size_t)bi * NN + q) * EE + h * HD;
#pragma unroll
        for (int ni = 0; ni < 8; ni++) {
            float2 val;
            val.x = oc[ni][rr*2]   * inv;
            val.y = oc[ni][rr*2+1] * inv;
            *(float2*)&g_ctx[rowoff + ni * 8 + 2 * tig] = val;
        }
    }
}

// ---------------------------------------------------------------------------
extern "C" void kernel_launch(void* const* d_in, const int* in_sizes, int n_in,
                              void* d_out, int out_size)
{
    const float* query = (const float*)d_in[0];
    const float* qkv_w = (const float*)d_in[1];
    const float* qkv_b = (const float*)d_in[2];
    const float* out_w = (const float*)d_in[3];
    const float* out_b = (const float*)d_in[4];
    float* out = (float*)d_out;

    const int attn_smem = 4 * 64 * 72 * 4;  // 73728 bytes
    cudaFuncSetAttribute(attn_k, cudaFuncAttributeMaxDynamicSharedMemorySize, attn_smem);

    gemm_k<0><<<dim3(18, 64), 256>>>(query, qkv_w, qkv_b, nullptr);
    attn_k<<<dim3(16, 96), 128, attn_smem>>>();
    gemm_k<1><<<dim3(6, 64), 256>>>(query, out_w, out_b, out);
}

// round 8
// speedup vs baseline: 1.0417x; 1.0417x over previous
#include <cuda_runtime.h>
#include <math.h>

#define BB 8
#define NN 1024
#define EE 768
#define HH 12
#define HD 64
#define GK 768

// Scratch (device globals: allocation-free per harness rules)
__device__ float g_q[(size_t)BB*HH*NN*HD];     // [B,H,N,64]  (tf32-rounded)
__device__ float g_k[(size_t)BB*HH*NN*HD];
__device__ float g_v[(size_t)BB*HH*NN*HD];
__device__ float g_ctx[(size_t)BB*NN*EE];      // [B*N, 768]  (tf32-rounded)

__device__ __forceinline__ unsigned f2tf(float x){
    unsigned r; asm("cvt.rna.tf32.f32 %0, %1;" : "=r"(r) : "f"(x)); return r;
}
__device__ __forceinline__ float f2tf_f(float x){ return __uint_as_float(f2tf(x)); }

__device__ __forceinline__ void mma8(float* c, const unsigned* a, const unsigned* b){
    asm volatile("mma.sync.aligned.m16n8k8.row.col.f32.tf32.tf32.f32 "
        "{%0,%1,%2,%3}, {%4,%5,%6,%7}, {%8,%9}, {%0,%1,%2,%3};\n"
        : "+f"(c[0]),"+f"(c[1]),"+f"(c[2]),"+f"(c[3])
        : "r"(a[0]),"r"(a[1]),"r"(a[2]),"r"(a[3]), "r"(b[0]),"r"(b[1]));
}

__device__ __forceinline__ void cpasync16(unsigned saddr, const void* gptr){
    asm volatile("cp.async.cg.shared.global [%0], [%1], 16;\n" :: "r"(saddr), "l"(gptr) : "memory");
}
__device__ __forceinline__ void cp_commit(){ asm volatile("cp.async.commit_group;\n" ::: "memory"); }
__device__ __forceinline__ void cp_wait0(){ asm volatile("cp.async.wait_group 0;\n" ::: "memory"); }

// ldmatrix x4: 4x (8 rows x 16B). For tf32, each 16B row = 4 tf32; reg i comes
// from matrix i at (row=lane>>2, col=lane&3). Matrices laid out as the four
// quadrants (rows 0-7/8-15) x (k 0-3/4-7) give exactly the m16n8k8 fragment.
__device__ __forceinline__ void ldsm4(unsigned* r, unsigned saddr){
    asm volatile("ldmatrix.sync.aligned.m8n8.x4.shared.b16 {%0,%1,%2,%3}, [%4];\n"
        : "=r"(r[0]),"=r"(r[1]),"=r"(r[2]),"=r"(r[3]) : "r"(saddr));
}

// ---------------------------------------------------------------------------
// NT GEMM: C[M,Ncols] = A[M,768] @ W[Ncols,768]^T + bias
// 128x128x32 tiles, 256 thr (8 warps 2x4), warp 64x32, tf32 HMMA.
// cp.async double-buffered staging (raw fp32; HW truncates to tf32 in MMA),
// ldmatrix fragments. smem stride 36 floats (row step 144B % 128 = 16 ->
// conflict-free LDSM). 2 CTAs/SM.
// MODE 0: A=query, N=2304, epilogue scatters tf32(acc+bias) into g_q/g_k/g_v.
// MODE 1: A=g_ctx, N=768, epilogue -> Cout fp32.
// ---------------------------------------------------------------------------
#define SA 36
#define STG_F (128*SA)          // floats per operand per stage (4608)
#define STAGE_F (2*STG_F)       // floats per stage (A+B)

template<int MODE>
__global__ void __launch_bounds__(256,2) gemm_k(
    const float* __restrict__ Ain, const float* __restrict__ Bw,
    const float* __restrict__ bias, float* __restrict__ Cout)
{
    extern __shared__ float sm[];
    const float* A = (MODE == 0) ? Ain : g_ctx;
    const unsigned smb = (unsigned)__cvta_generic_to_shared(sm);

    const int t = threadIdx.x;
    const int lane = t & 31, wid = t >> 5;
    const int group = lane >> 2, tig = lane & 3;
    const int wm = wid >> 2, wn = wid & 3;
    const int m0 = blockIdx.y * 128, n0 = blockIdx.x * 128;

    // loader mapping: 128 rows x 32 floats per operand; thread -> 1 row, 16 floats
    const int lrow = t >> 1;
    const int lc = (t & 1) * 16;
    const float* agbase = A  + (size_t)(m0 + lrow) * GK + lc;
    const float* bgbase = Bw + (size_t)(n0 + lrow) * GK + lc;
    const unsigned sArow = smb + (unsigned)(lrow * SA + lc) * 4u;

    auto load_stage = [&](int kt, int s){
        const float* ag = agbase + kt * 32;
        const float* bg = bgbase + kt * 32;
        const unsigned sa = sArow + (unsigned)(s * STAGE_F) * 4u;
        const unsigned sb = sa + STG_F * 4u;
#pragma unroll
        for (int j = 0; j < 4; j++) {
            cpasync16(sa + j * 16u, ag + j * 4);
            cpasync16(sb + j * 16u, bg + j * 4);
        }
        cp_commit();
    };

    float acc[4][4][4];
#pragma unroll
    for (int mi = 0; mi < 4; mi++)
#pragma unroll
        for (int ni = 0; ni < 4; ni++)
#pragma unroll
            for (int v = 0; v < 4; v++) acc[mi][ni][v] = 0.f;

    // ldmatrix lane geometry
    const int q8 = lane >> 3, r8 = lane & 7;
    const int a_row = wm * 64 + ((q8 & 1) << 3) + r8;   // + mi*16
    const int b_row = wn * 32 + ((q8 & 1) << 3) + r8;   // + p*16
    const int colb  = (q8 >> 1) * 4;                    // + kb

    const int KT = GK / 32;  // 24
    load_stage(0, 0);

#pragma unroll 1
    for (int kt = 0; kt < KT; kt++) {
        cp_wait0();
        __syncthreads();
        if (kt + 1 < KT) load_stage(kt + 1, (kt + 1) & 1);

        const unsigned aB = smb + (unsigned)((kt & 1) * STAGE_F) * 4u;
        const unsigned bB = aB + STG_F * 4u;
#pragma unroll
        for (int ks = 0; ks < 4; ks++) {
            const int kb = ks * 8;
            unsigned af[4][4], br[2][4];
#pragma unroll
            for (int mi = 0; mi < 4; mi++)
                ldsm4(af[mi], aB + (unsigned)((a_row + mi * 16) * SA + colb + kb) * 4u);
#pragma unroll
            for (int p = 0; p < 2; p++)
                ldsm4(br[p], bB + (unsigned)((b_row + p * 16) * SA + colb + kb) * 4u);
#pragma unroll
            for (int mi = 0; mi < 4; mi++)
#pragma unroll
                for (int ni = 0; ni < 4; ni++) {
                    unsigned bb[2] = { br[ni >> 1][ni & 1], br[ni >> 1][(ni & 1) + 2] };
                    mma8(acc[mi][ni], af[mi], bb);
                }
        }
        __syncthreads();
    }

    // epilogue
    float bv0[4], bv1[4];
#pragma unroll
    for (int ni = 0; ni < 4; ni++) {
        const int c = n0 + wn * 32 + ni * 8 + 2 * tig;
        bv0[ni] = bias[c]; bv1[ni] = bias[c + 1];
    }

    if (MODE == 0) {
        const int which = blockIdx.x / 6;   // 0=q 1=k 2=v
        float* dstbuf = (which == 0) ? g_q : ((which == 1) ? g_k : g_v);
#pragma unroll
        for (int mi = 0; mi < 4; mi++)
#pragma unroll
            for (int rr = 0; rr < 2; rr++) {
                const int r  = m0 + wm * 64 + mi * 16 + group + rr * 8;
                const int bi = r >> 10, nidx = r & 1023;
#pragma unroll
                for (int ni = 0; ni < 4; ni++) {
                    const int c = n0 + wn * 32 + ni * 8 + 2 * tig;
                    const int e = c - which * 768;
                    const int h = e >> 6, d = e & 63;
                    float2 val;
                    val.x = f2tf_f(acc[mi][ni][rr*2+0] + bv0[ni]);
                    val.y = f2tf_f(acc[mi][ni][rr*2+1] + bv1[ni]);
                    *(float2*)&dstbuf[(((size_t)bi * HH + h) * NN + nidx) * HD + d] = val;
                }
            }
    } else {
#pragma unroll
        for (int mi = 0; mi < 4; mi++)
#pragma unroll
            for (int rr = 0; rr < 2; rr++) {
                const int r = m0 + wm * 64 + mi * 16 + group + rr * 8;
#pragma unroll
                for (int ni = 0; ni < 4; ni++) {
                    const int c = n0 + wn * 32 + ni * 8 + 2 * tig;
                    float2 val;
                    val.x = acc[mi][ni][rr*2+0] + bv0[ni];
                    val.y = acc[mi][ni][rr*2+1] + bv1[ni];
                    *(float2*)&Cout[(size_t)r * EE + c] = val;
                }
            }
    }
}

// ---------------------------------------------------------------------------
// Flash attention v2: 256 thr (8 warps x 16 q-rows), q-tile 128, key-tile 64.
// Qs[128][68] row-major (pre-scaled, already tf32), Ks[64][68] (cp.async),
// Vs[64][72] (cp.async, conflict-free scalar B loads), Ps[128][68].
// ldmatrix for Q/K/P fragments; scalar LDS only for V. 2 CTAs/SM.
// ---------------------------------------------------------------------------
#define QS_F (128*68)
#define KS_F (64*68)
#define VS_F (64*72)

__global__ void __launch_bounds__(256,2) attn_k()
{
    extern __shared__ float sm[];
    float* Qs = sm;
    float* Vs = sm + QS_F + KS_F;
    float* Ps = Vs + VS_F;
    const unsigned smb = (unsigned)__cvta_generic_to_shared(sm);
    const unsigned KsU = smb + QS_F * 4u;
    const unsigned VsU = KsU + KS_F * 4u;
    const unsigned PsU = VsU + VS_F * 4u;

    const int t = threadIdx.x, lane = t & 31, wid = t >> 5;
    const int group = lane >> 2, tig = lane & 3;
    const int bh = blockIdx.y, qt = blockIdx.x;

    {   // stage Q (tf32 already; pre-scale by 1/sqrt(64) = exact exponent shift)
        const size_t baseQ = ((size_t)bh * NN + qt * 128) * HD;
#pragma unroll
        for (int i = 0; i < 8; i++) {
            const int idx = t + i * 256;
            const int row = idx >> 4, d4 = (idx & 15) * 4;
            float4 v = *(const float4*)&g_q[baseQ + row * 64 + d4];
            Qs[row*68 + d4+0] = v.x * 0.125f;
            Qs[row*68 + d4+1] = v.y * 0.125f;
            Qs[row*68 + d4+2] = v.z * 0.125f;
            Qs[row*68 + d4+3] = v.w * 0.125f;
        }
    }

    float oc[8][4];
#pragma unroll
    for (int ni = 0; ni < 8; ni++)
#pragma unroll
        for (int v = 0; v < 4; v++) oc[ni][v] = 0.f;
    float mprev[2] = {-1e30f, -1e30f};
    float lsum[2]  = {0.f, 0.f};

    // cp.async mapping for K/V: 64 rows x 64 floats; thread -> row t>>2, 16 floats
    const int krow = t >> 2;
    const int kcf  = (t & 3) * 16;
    const unsigned ksAddr = KsU + (unsigned)(krow * 68 + kcf) * 4u;
    const unsigned vsAddr = VsU + (unsigned)(krow * 72 + kcf) * 4u;

    // ldmatrix lane geometry
    const int q8 = lane >> 3, r8 = lane & 7;
    const int a_row = wid * 16 + ((q8 & 1) << 3) + r8;
    const int colb  = (q8 >> 1) * 4;
    const int b_rowk = ((q8 & 1) << 3) + r8;            // + p*16, into Ks

#pragma unroll 1
    for (int kt = 0; kt < 16; kt++) {
        __syncthreads();   // all warps done with prev Ks/Vs (and Qs staged on kt=0)
        {
            const size_t baseK = ((size_t)bh * NN + kt * 64) * HD + krow * 64 + kcf;
            const float* gk = g_k + baseK;
            const float* gv = g_v + baseK;
#pragma unroll
            for (int j = 0; j < 4; j++) {
                cpasync16(ksAddr + j * 16u, gk + j * 4);
                cpasync16(vsAddr + j * 16u, gv + j * 4);
            }
            cp_commit(); cp_wait0();
        }
        __syncthreads();

        // S = Q K^T : per warp 16 q-rows x 64 keys
        float sc[8][4];
#pragma unroll
        for (int ni = 0; ni < 8; ni++)
#pragma unroll
            for (int v = 0; v < 4; v++) sc[ni][v] = 0.f;
#pragma unroll
        for (int ks = 0; ks < 8; ks++) {
            const int kb = ks * 8;
            unsigned a[4];
            ldsm4(a, smb + (unsigned)(a_row * 68 + colb + kb) * 4u);
#pragma unroll
            for (int p = 0; p < 4; p++) {
                unsigned br[4];
                ldsm4(br, KsU + (unsigned)((b_rowk + p * 16) * 68 + colb + kb) * 4u);
                unsigned b0[2] = { br[0], br[2] };
                unsigned b1[2] = { br[1], br[3] };
                mma8(sc[2*p],   a, b0);
                mma8(sc[2*p+1], a, b1);
            }
        }

        // online softmax (rows group and group+8; stats across lane quad)
#pragma unroll
        for (int rr = 0; rr < 2; rr++) {
            float tm = -1e30f;
#pragma unroll
            for (int ni = 0; ni < 8; ni++)
                tm = fmaxf(tm, fmaxf(sc[ni][rr*2], sc[ni][rr*2+1]));
            tm = fmaxf(tm, __shfl_xor_sync(0xffffffffu, tm, 1));
            tm = fmaxf(tm, __shfl_xor_sync(0xffffffffu, tm, 2));
            const float mnew = fmaxf(mprev[rr], tm);
            const float corr = __expf(mprev[rr] - mnew);
            mprev[rr] = mnew;
            float rs = 0.f;
#pragma unroll
            for (int ni = 0; ni < 8; ni++) {
                const float p0 = __expf(sc[ni][rr*2]   - mnew);
                const float p1 = __expf(sc[ni][rr*2+1] - mnew);
                sc[ni][rr*2] = p0; sc[ni][rr*2+1] = p1;
                rs += p0 + p1;
            }
            rs += __shfl_xor_sync(0xffffffffu, rs, 1);
            rs += __shfl_xor_sync(0xffffffffu, rs, 2);
            lsum[rr] = lsum[rr] * corr + rs;
#pragma unroll
            for (int ni = 0; ni < 8; ni++) {
                oc[ni][rr*2]   *= corr;
                oc[ni][rr*2+1] *= corr;
            }
        }

        // stage P row-major [m][key] (raw fp32; MMA truncates to tf32)
        {
            const int row0 = wid * 16 + group;
#pragma unroll
            for (int ni = 0; ni < 8; ni++) {
                const int col = ni * 8 + 2 * tig;
                float2 v0 = { sc[ni][0], sc[ni][1] };
                float2 v1 = { sc[ni][2], sc[ni][3] };
                *(float2*)&Ps[row0 * 68 + col]       = v0;
                *(float2*)&Ps[(row0 + 8) * 68 + col] = v1;
            }
        }
        __syncwarp();

        // O += P V   (A via ldmatrix on own rows; B via conflict-free scalar LDS)
#pragma unroll
        for (int ks = 0; ks < 8; ks++) {
            const int kb = ks * 8;
            unsigned a[4];
            ldsm4(a, PsU + (unsigned)(a_row * 68 + colb + kb) * 4u);
#pragma unroll
            for (int ni = 0; ni < 8; ni++) {
                unsigned b[2];
                b[0] = __float_as_uint(Vs[(kb+tig  )*72 + ni*8+group]);
                b[1] = __float_as_uint(Vs[(kb+tig+4)*72 + ni*8+group]);
                mma8(oc[ni], a, b);
            }
        }
    }

    // normalize + write ctx [B*N, 768] at column h*64 (tf32-rounded for GEMM1)
    const int bi = bh / HH, h = bh % HH;
#pragma unroll
    for (int rr = 0; rr < 2; rr++) {
        const float inv = 1.0f / lsum[rr];
        const int qrow = qt * 128 + wid * 16 + group + rr * 8;
        const size_t rowoff = ((size_t)bi * NN + qrow) * EE + h * HD;
#pragma unroll
        for (int ni = 0; ni < 8; ni++) {
            float2 val;
            val.x = f2tf_f(oc[ni][rr*2]   * inv);
            val.y = f2tf_f(oc[ni][rr*2+1] * inv);
            *(float2*)&g_ctx[rowoff + ni * 8 + 2 * tig] = val;
        }
    }
}

// ---------------------------------------------------------------------------
extern "C" void kernel_launch(void* const* d_in, const int* in_sizes, int n_in,
                              void* d_out, int out_size)
{
    const float* query = (const float*)d_in[0];
    const float* qkv_w = (const float*)d_in[1];
    const float* qkv_b = (const float*)d_in[2];
    const float* out_w = (const float*)d_in[3];
    const float* out_b = (const float*)d_in[4];
    float* out = (float*)d_out;

    const int gemm_smem = 2 * STAGE_F * 4;                       // 73728 B
    const int attn_smem = (QS_F + KS_F + VS_F + 128*68) * 4;     // 105472 B
    cudaFuncSetAttribute(gemm_k<0>, cudaFuncAttributeMaxDynamicSharedMemorySize, gemm_smem);
    cudaFuncSetAttribute(gemm_k<1>, cudaFuncAttributeMaxDynamicSharedMemorySize, gemm_smem);
    cudaFuncSetAttribute(attn_k,    cudaFuncAttributeMaxDynamicSharedMemorySize, attn_smem);

    gemm_k<0><<<dim3(18, 64), 256, gemm_smem>>>(query, qkv_w, qkv_b, nullptr);
    attn_k<<<dim3(8, 96), 256, attn_smem>>>();
    gemm_k<1><<<dim3(6, 64), 256, gemm_smem>>>(query, out_w, out_b, out);
}

// round 10
// speedup vs baseline: 2.5312x; 2.4298x over previous
#include <cuda_runtime.h>
#include <cuda_fp16.h>
#include <math.h>

#define BB 8
#define NN 1024
#define EE 768
#define HH 12
#define HD 64
#define GK 768

// fp16 scratch (device globals: allocation-free per harness rules)
__device__ __half g_query16[(size_t)BB*NN*EE];   // [8192,768]
__device__ __half g_qkvw16[(size_t)3*EE*EE];     // [2304,768]
__device__ __half g_outw16[(size_t)EE*EE];       // [768,768]
__device__ __half g_q16[(size_t)BB*HH*NN*HD];    // [B,H,N,64]  (pre-scaled 1/8)
__device__ __half g_k16[(size_t)BB*HH*NN*HD];    // [B,H,N,64]
__device__ __half g_vT16[(size_t)BB*HH*HD*NN];   // [B,H,64,N]  (transposed!)
__device__ __half g_ctx16[(size_t)BB*NN*EE];     // [8192,768]

__device__ __forceinline__ void mma16(float* c, const unsigned* a, const unsigned* b){
    asm volatile("mma.sync.aligned.m16n8k16.row.col.f32.f16.f16.f32 "
        "{%0,%1,%2,%3}, {%4,%5,%6,%7}, {%8,%9}, {%0,%1,%2,%3};\n"
        : "+f"(c[0]),"+f"(c[1]),"+f"(c[2]),"+f"(c[3])
        : "r"(a[0]),"r"(a[1]),"r"(a[2]),"r"(a[3]), "r"(b[0]),"r"(b[1]));
}
__device__ __forceinline__ void cpasync16(unsigned saddr, const void* gptr){
    asm volatile("cp.async.cg.shared.global [%0], [%1], 16;\n" :: "r"(saddr), "l"(gptr) : "memory");
}
__device__ __forceinline__ void cp_commit(){ asm volatile("cp.async.commit_group;\n" ::: "memory"); }
__device__ __forceinline__ void cp_wait0(){ asm volatile("cp.async.wait_group 0;\n" ::: "memory"); }
__device__ __forceinline__ void cp_wait1(){ asm volatile("cp.async.wait_group 1;\n" ::: "memory"); }
__device__ __forceinline__ void ldsm4(unsigned* r, unsigned saddr){
    asm volatile("ldmatrix.sync.aligned.m8n8.x4.shared.b16 {%0,%1,%2,%3}, [%4];\n"
        : "=r"(r[0]),"=r"(r[1]),"=r"(r[2]),"=r"(r[3]) : "r"(saddr));
}
__device__ __forceinline__ unsigned swz(unsigned x){ return x ^ ((x >> 3) & 0x70); }

// ---------------------------------------------------------------------------
// fp32 -> fp16 pre-convert (query, qkv_w, out_w), float4 -> 2x half2
// ---------------------------------------------------------------------------
__global__ void cvt_k(const float* __restrict__ q, const float* __restrict__ w1,
                      const float* __restrict__ w2)
{
    const int NQ = (BB*NN*EE)/4, NW1 = (3*EE*EE)/4, NW2 = (EE*EE)/4;
    const int stride = gridDim.x * blockDim.x;
    int i = blockIdx.x * blockDim.x + threadIdx.x;
    for (int j = i; j < NQ; j += stride) {
        float4 v = ((const float4*)q)[j];
        __half2 h0 = __floats2half2_rn(v.x, v.y), h1 = __floats2half2_rn(v.z, v.w);
        ((uint2*)g_query16)[j] = make_uint2(*(unsigned*)&h0, *(unsigned*)&h1);
    }
    for (int j = i; j < NW1; j += stride) {
        float4 v = ((const float4*)w1)[j];
        __half2 h0 = __floats2half2_rn(v.x, v.y), h1 = __floats2half2_rn(v.z, v.w);
        ((uint2*)g_qkvw16)[j] = make_uint2(*(unsigned*)&h0, *(unsigned*)&h1);
    }
    for (int j = i; j < NW2; j += stride) {
        float4 v = ((const float4*)w2)[j];
        __half2 h0 = __floats2half2_rn(v.x, v.y), h1 = __floats2half2_rn(v.z, v.w);
        ((uint2*)g_outw16)[j] = make_uint2(*(unsigned*)&h0, *(unsigned*)&h1);
    }
}

// ---------------------------------------------------------------------------
// fp16 NT GEMM: C[M,Ncols] = A[M,768] @ W[Ncols,768]^T + bias
// CTA 128x128, 256 thr (8 warps 2x4), warp 64x32, mma m16n8k16 f16->f32.
// k-chunks of 64 halves (128B rows, SW128 swizzle), 3-stage cp.async ring,
// ONE __syncthreads per k-iter. MODE 0: scatter to g_q16 (x0.125) / g_k16 /
// g_vT16 (transposed). MODE 1: fp32 out + bias.
// ---------------------------------------------------------------------------
#define TILE_B  (128*128)          // bytes per operand tile (128 rows x 128B)
#define STAGE_B (2*TILE_B)         // 32768 B
#define GSM     (3*STAGE_B)        // 98304 B
#define KT16    (GK/64)            // 12

template<int MODE>
__global__ void __launch_bounds__(256,2) gemm_k(
    const __half* __restrict__ Bw, const float* __restrict__ bias,
    float* __restrict__ Cout)
{
    extern __shared__ char smc[];
    const unsigned smb = (unsigned)__cvta_generic_to_shared(smc);
    const __half* A = (MODE == 0) ? g_query16 : g_ctx16;

    const int t = threadIdx.x;
    const int lane = t & 31, wid = t >> 5;
    const int group = lane >> 2, tig = lane & 3;
    const int wm = wid >> 2, wn = wid & 3;
    const int m0 = blockIdx.y * 128, n0 = blockIdx.x * 128;

    // loader: 1024 16B-segs per operand, 4 per thread: s = t + j*256
    auto load_stage = [&](int kt, int st){
        const unsigned ab = smb + (unsigned)st * STAGE_B;
        const unsigned bb = ab + TILE_B;
#pragma unroll
        for (int j = 0; j < 4; j++) {
            const int s = t + j * 256;
            const int row = s >> 3, c16 = s & 7;
            const unsigned off = swz((unsigned)(row * 128 + c16 * 16));
            const size_t go = (size_t)row * GK + kt * 64 + c16 * 8;
            cpasync16(ab + off, A  + (size_t)m0 * GK + go);
            cpasync16(bb + off, Bw + (size_t)n0 * GK + go);
        }
        cp_commit();
    };

    float acc[4][4][4];
#pragma unroll
    for (int mi = 0; mi < 4; mi++)
#pragma unroll
        for (int ni = 0; ni < 4; ni++)
#pragma unroll
            for (int v = 0; v < 4; v++) acc[mi][ni][v] = 0.f;

    const int l16 = lane & 15, lh = lane >> 4;   // ldsm row / 16B col-half

    load_stage(0, 0);
    load_stage(1, 1);

#pragma unroll 1
    for (int kt = 0; kt < KT16; kt++) {
        if (kt + 1 < KT16) cp_wait1(); else cp_wait0();
        __syncthreads();
        if (kt + 2 < KT16) load_stage(kt + 2, (kt + 2) % 3);

        const unsigned ab = smb + (unsigned)(kt % 3) * STAGE_B;
        const unsigned bb = ab + TILE_B;
#pragma unroll
        for (int ks = 0; ks < 4; ks++) {
            unsigned af[4][4], br[2][4];
#pragma unroll
            for (int mi = 0; mi < 4; mi++) {
                const int row = wm * 64 + mi * 16 + l16;
                ldsm4(af[mi], ab + swz((unsigned)(row * 128 + lh * 16 + ks * 32)));
            }
#pragma unroll
            for (int p = 0; p < 2; p++) {
                const int row = wn * 32 + p * 16 + l16;
                ldsm4(br[p], bb + swz((unsigned)(row * 128 + lh * 16 + ks * 32)));
            }
#pragma unroll
            for (int mi = 0; mi < 4; mi++)
#pragma unroll
                for (int ni = 0; ni < 4; ni++) {
                    unsigned bfr[2] = { br[ni >> 1][ni & 1], br[ni >> 1][(ni & 1) + 2] };
                    mma16(acc[mi][ni], af[mi], bfr);
                }
        }
        __syncthreads();
    }

    // epilogue
    float bv0[4], bv1[4];
#pragma unroll
    for (int ni = 0; ni < 4; ni++) {
        const int c = n0 + wn * 32 + ni * 8 + 2 * tig;
        bv0[ni] = bias[c]; bv1[ni] = bias[c + 1];
    }

    if (MODE == 0) {
        const int which = blockIdx.x / 6;   // 0=q 1=k 2=v
        const float qs = (which == 0) ? 0.125f : 1.0f;
#pragma unroll
        for (int mi = 0; mi < 4; mi++)
#pragma unroll
            for (int rr = 0; rr < 2; rr++) {
                const int r  = m0 + wm * 64 + mi * 16 + group + rr * 8;
                const int bi = r >> 10, nidx = r & 1023;
#pragma unroll
                for (int ni = 0; ni < 4; ni++) {
                    const int c = n0 + wn * 32 + ni * 8 + 2 * tig;
                    const int e = c - which * 768;
                    const int h = e >> 6, d = e & 63;
                    const float vx = (acc[mi][ni][rr*2+0] + bv0[ni]) * qs;
                    const float vy = (acc[mi][ni][rr*2+1] + bv1[ni]) * qs;
                    if (which == 2) {
                        const size_t base = (((size_t)bi * HH + h) * HD + d) * NN + nidx;
                        g_vT16[base]      = __float2half_rn(vx);
                        g_vT16[base + NN] = __float2half_rn(vy);
                    } else {
                        __half* dst = (which == 0 ? g_q16 : g_k16)
                                    + ((((size_t)bi * HH + h) * NN + nidx) * HD + d);
                        *(__half2*)dst = __floats2half2_rn(vx, vy);
                    }
                }
            }
    } else {
#pragma unroll
        for (int mi = 0; mi < 4; mi++)
#pragma unroll
            for (int rr = 0; rr < 2; rr++) {
                const int r = m0 + wm * 64 + mi * 16 + group + rr * 8;
#pragma unroll
                for (int ni = 0; ni < 4; ni++) {
                    const int c = n0 + wn * 32 + ni * 8 + 2 * tig;
                    float2 val;
                    val.x = acc[mi][ni][rr*2+0] + bv0[ni];
                    val.y = acc[mi][ni][rr*2+1] + bv1[ni];
                    *(float2*)&Cout[(size_t)r * EE + c] = val;
                }
            }
    }
}

// ---------------------------------------------------------------------------
// Flash attention fp16: 256 thr (8 warps x 16 q-rows), q-tile 128, key-tile 64.
// Qs[128][64h] (pre-scaled), Ks[2][64][64h], VTs[2][64 d][64 keys] (double-
// buffered cp.async), Ps[128][64h]. All 128B swizzled rows. mma m16n8k16.
// ---------------------------------------------------------------------------
#define ATT_Q   0
#define ATT_K0  16384
#define ATT_V0  32768
#define ATT_P   49152
#define ATT_SM  65536

__global__ void __launch_bounds__(256,2) attn_k()
{
    extern __shared__ char smc[];
    const unsigned smb = (unsigned)__cvta_generic_to_shared(smc);

    const int t = threadIdx.x, lane = t & 31, wid = t >> 5;
    const int group = lane >> 2, tig = lane & 3;
    const int l16 = lane & 15, lh = lane >> 4;
    const int bh = blockIdx.y, qt = blockIdx.x;

    // K/V tile loader: 512 16B-segs each, 2 per thread
    auto load_kv = [&](int kt, int st){
        const unsigned kb = smb + ATT_K0 + (unsigned)st * 8192u;
        const unsigned vb = smb + ATT_V0 + (unsigned)st * 8192u;
#pragma unroll
        for (int j = 0; j < 2; j++) {
            const int s = t + j * 256;
            const int row = s >> 3, c16 = s & 7;
            const unsigned off = swz((unsigned)(row * 128 + c16 * 16));
            cpasync16(kb + off, g_k16  + ((size_t)bh * NN + kt * 64 + row) * HD + c16 * 8);
            cpasync16(vb + off, g_vT16 + ((size_t)bh * HD + row) * NN + kt * 64 + c16 * 8);
        }
        cp_commit();
    };

    {   // stage Q (1024 segs, 4/thread) + K/V tile 0 in ONE group
        const __half* gq = g_q16 + ((size_t)bh * NN + qt * 128) * HD;
#pragma unroll
        for (int j = 0; j < 4; j++) {
            const int s = t + j * 256;
            const int row = s >> 3, c16 = s & 7;
            cpasync16(smb + ATT_Q + swz((unsigned)(row * 128 + c16 * 16)),
                      gq + (size_t)row * HD + c16 * 8);
        }
        load_kv(0, 0);   // commits the combined group
    }

    float oc[8][4];
#pragma unroll
    for (int ni = 0; ni < 8; ni++)
#pragma unroll
        for (int v = 0; v < 4; v++) oc[ni][v] = 0.f;
    float mprev[2] = {-1e30f, -1e30f};
    float lsum[2]  = {0.f, 0.f};

#pragma unroll 1
    for (int kt = 0; kt < 16; kt++) {
        if (kt + 1 < 16) { load_kv(kt + 1, (kt + 1) & 1); cp_wait1(); }
        else             { cp_wait0(); }
        __syncthreads();

        const unsigned kb = smb + ATT_K0 + (unsigned)(kt & 1) * 8192u;
        const unsigned vb = smb + ATT_V0 + (unsigned)(kt & 1) * 8192u;

        // S = Q K^T : per warp 16 q-rows x 64 keys (k = d, 4 steps of 16)
        float sc[8][4];
#pragma unroll
        for (int ni = 0; ni < 8; ni++)
#pragma unroll
            for (int v = 0; v < 4; v++) sc[ni][v] = 0.f;
#pragma unroll
        for (int ks = 0; ks < 4; ks++) {
            unsigned a[4];
            ldsm4(a, smb + ATT_Q + swz((unsigned)((wid * 16 + l16) * 128 + lh * 16 + ks * 32)));
#pragma unroll
            for (int p = 0; p < 4; p++) {
                unsigned br[4];
                ldsm4(br, kb + swz((unsigned)((p * 16 + l16) * 128 + lh * 16 + ks * 32)));
                unsigned b0[2] = { br[0], br[2] };
                unsigned b1[2] = { br[1], br[3] };
                mma16(sc[2*p],   a, b0);
                mma16(sc[2*p+1], a, b1);
            }
        }

        // online softmax (rows group, group+8; stats across lane quad)
#pragma unroll
        for (int rr = 0; rr < 2; rr++) {
            float tm = -1e30f;
#pragma unroll
            for (int ni = 0; ni < 8; ni++)
                tm = fmaxf(tm, fmaxf(sc[ni][rr*2], sc[ni][rr*2+1]));
            tm = fmaxf(tm, __shfl_xor_sync(0xffffffffu, tm, 1));
            tm = fmaxf(tm, __shfl_xor_sync(0xffffffffu, tm, 2));
            const float mnew = fmaxf(mprev[rr], tm);
            const float corr = __expf(mprev[rr] - mnew);
            mprev[rr] = mnew;
            float rs = 0.f;
#pragma unroll
            for (int ni = 0; ni < 8; ni++) {
                const float p0 = __expf(sc[ni][rr*2]   - mnew);
                const float p1 = __expf(sc[ni][rr*2+1] - mnew);
                sc[ni][rr*2] = p0; sc[ni][rr*2+1] = p1;
                rs += p0 + p1;
            }
            rs += __shfl_xor_sync(0xffffffffu, rs, 1);
            rs += __shfl_xor_sync(0xffffffffu, rs, 2);
            lsum[rr] = lsum[rr] * corr + rs;
#pragma unroll
            for (int ni = 0; ni < 8; ni++) {
                oc[ni][rr*2]   *= corr;
                oc[ni][rr*2+1] *= corr;
            }
        }

        // stage P as half2 [m][key] (own warp's rows only)
        {
            const int row0 = wid * 16 + group;
#pragma unroll
            for (int ni = 0; ni < 8; ni++) {
                const int col = ni * 8 + 2 * tig;
                __half2 v0 = __floats2half2_rn(sc[ni][0], sc[ni][1]);
                __half2 v1 = __floats2half2_rn(sc[ni][2], sc[ni][3]);
                *(__half2*)(smc + ATT_P + swz((unsigned)( row0      * 128 + col * 2))) = v0;
                *(__half2*)(smc + ATT_P + swz((unsigned)((row0 + 8) * 128 + col * 2))) = v1;
            }
        }
        __syncwarp();

        // O += P V  (A = P rows, B = V^T rows d; k = keys, 4 steps of 16)
#pragma unroll
        for (int ks = 0; ks < 4; ks++) {
            unsigned a[4];
            ldsm4(a, smb + ATT_P + swz((unsigned)((wid * 16 + l16) * 128 + lh * 16 + ks * 32)));
#pragma unroll
            for (int p = 0; p < 4; p++) {
                unsigned br[4];
                ldsm4(br, vb + swz((unsigned)((p * 16 + l16) * 128 + lh * 16 + ks * 32)));
                unsigned b0[2] = { br[0], br[2] };
                unsigned b1[2] = { br[1], br[3] };
                mma16(oc[2*p],   a, b0);
                mma16(oc[2*p+1], a, b1);
            }
        }
        __syncthreads();   // protect K/V buffer reuse by next-next load
    }

    // normalize + write ctx16 [8192,768] at col h*64
    const int bi = bh / HH, h = bh % HH;
#pragma unroll
    for (int rr = 0; rr < 2; rr++) {
        const float inv = 1.0f / lsum[rr];
        const int qrow = qt * 128 + wid * 16 + group + rr * 8;
        const size_t rowoff = ((size_t)bi * NN + qrow) * EE + h * HD;
#pragma unroll
        for (int ni = 0; ni < 8; ni++) {
            __half2 v = __floats2half2_rn(oc[ni][rr*2] * inv, oc[ni][rr*2+1] * inv);
            *(__half2*)&g_ctx16[rowoff + ni * 8 + 2 * tig] = v;
        }
    }
}

// ---------------------------------------------------------------------------
extern "C" void kernel_launch(void* const* d_in, const int* in_sizes, int n_in,
                              void* d_out, int out_size)
{
    const float* query = (const float*)d_in[0];
    const float* qkv_w = (const float*)d_in[1];
    const float* qkv_b = (const float*)d_in[2];
    const float* out_w = (const float*)d_in[3];
    const float* out_b = (const float*)d_in[4];
    float* out = (float*)d_out;

    cudaFuncSetAttribute(gemm_k<0>, cudaFuncAttributeMaxDynamicSharedMemorySize, GSM);
    cudaFuncSetAttribute(gemm_k<1>, cudaFuncAttributeMaxDynamicSharedMemorySize, GSM);
    cudaFuncSetAttribute(attn_k,    cudaFuncAttributeMaxDynamicSharedMemorySize, ATT_SM);

    // resolve the fp16 weight scratch device addresses (host-side, cheap)
    static __half *w1p = nullptr, *w2p = nullptr;
    if (!w1p) { cudaGetSymbolAddress((void**)&w1p, g_qkvw16);
                cudaGetSymbolAddress((void**)&w2p, g_outw16); }

    cvt_k<<<1024, 256>>>(query, qkv_w, out_w);
    gemm_k<0><<<dim3(18, 64), 256, GSM>>>(w1p, qkv_b, nullptr);
    attn_k<<<dim3(8, 96), 256, ATT_SM>>>();
    gemm_k<1><<<dim3(6, 64), 256, GSM>>>(w2p, out_b, out);
}

// round 13
// speedup vs baseline: 2.6875x; 1.0617x over previous
#include <cuda_runtime.h>
#include <cuda_fp16.h>
#include <math.h>

#define BB 8
#define NN 1024
#define EE 768
#define HH 12
#define HD 64
#define GK 768

// fp16 scratch (device globals: allocation-free per harness rules)
__device__ __half g_query16[(size_t)BB*NN*EE];   // [8192,768]
__device__ __half g_qkvw16[(size_t)3*EE*EE];     // [2304,768]
__device__ __half g_outw16[(size_t)EE*EE];       // [768,768]
__device__ __half g_q16[(size_t)BB*HH*NN*HD];    // [B,H,N,64]  (pre-scaled 1/8)
__device__ __half g_k16[(size_t)BB*HH*NN*HD];    // [B,H,N,64]
__device__ __half g_vT16[(size_t)BB*HH*HD*NN];   // [B,H,64,N]  (transposed!)
__device__ __half g_ctx16[(size_t)BB*NN*EE];     // [8192,768]

__device__ __forceinline__ void mma16(float* c, const unsigned* a, const unsigned* b){
    asm volatile("mma.sync.aligned.m16n8k16.row.col.f32.f16.f16.f32 "
        "{%0,%1,%2,%3}, {%4,%5,%6,%7}, {%8,%9}, {%0,%1,%2,%3};\n"
        : "+f"(c[0]),"+f"(c[1]),"+f"(c[2]),"+f"(c[3])
        : "r"(a[0]),"r"(a[1]),"r"(a[2]),"r"(a[3]), "r"(b[0]),"r"(b[1]));
}
__device__ __forceinline__ void cpasync16(unsigned saddr, const void* gptr){
    asm volatile("cp.async.cg.shared.global [%0], [%1], 16;\n" :: "r"(saddr), "l"(gptr) : "memory");
}
__device__ __forceinline__ void cp_commit(){ asm volatile("cp.async.commit_group;\n" ::: "memory"); }
__device__ __forceinline__ void cp_wait0(){ asm volatile("cp.async.wait_group 0;\n" ::: "memory"); }
__device__ __forceinline__ void cp_wait1(){ asm volatile("cp.async.wait_group 1;\n" ::: "memory"); }
__device__ __forceinline__ void ldsm4(unsigned* r, unsigned saddr){
    asm volatile("ldmatrix.sync.aligned.m8n8.x4.shared.b16 {%0,%1,%2,%3}, [%4];\n"
        : "=r"(r[0]),"=r"(r[1]),"=r"(r[2]),"=r"(r[3]) : "r"(saddr));
}
__device__ __forceinline__ unsigned swz(unsigned x){ return x ^ ((x >> 3) & 0x70); }

// ---------------------------------------------------------------------------
// fp32 -> fp16 pre-convert (query, qkv_w, out_w)
// ---------------------------------------------------------------------------
__global__ void cvt_k(const float* __restrict__ q, const float* __restrict__ w1,
                      const float* __restrict__ w2)
{
    const int NQ = (BB*NN*EE)/4, NW1 = (3*EE*EE)/4, NW2 = (EE*EE)/4;
    const int stride = gridDim.x * blockDim.x;
    int i = blockIdx.x * blockDim.x + threadIdx.x;
    for (int j = i; j < NQ; j += stride) {
        float4 v = ((const float4*)q)[j];
        __half2 h0 = __floats2half2_rn(v.x, v.y), h1 = __floats2half2_rn(v.z, v.w);
        ((uint2*)g_query16)[j] = make_uint2(*(unsigned*)&h0, *(unsigned*)&h1);
    }
    for (int j = i; j < NW1; j += stride) {
        float4 v = ((const float4*)w1)[j];
        __half2 h0 = __floats2half2_rn(v.x, v.y), h1 = __floats2half2_rn(v.z, v.w);
        ((uint2*)g_qkvw16)[j] = make_uint2(*(unsigned*)&h0, *(unsigned*)&h1);
    }
    for (int j = i; j < NW2; j += stride) {
        float4 v = ((const float4*)w2)[j];
        __half2 h0 = __floats2half2_rn(v.x, v.y), h1 = __floats2half2_rn(v.z, v.w);
        ((uint2*)g_outw16)[j] = make_uint2(*(unsigned*)&h0, *(unsigned*)&h1);
    }
}

// ---------------------------------------------------------------------------
// fp16 NT GEMM: C[M,Ncols] = A[M,768] @ W[Ncols,768]^T + bias
// CTA 128x128, 128 thr (4 warps 2x2), warp 64x64, mma m16n8k16 f16->f32.
// k-chunks of 64 halves (128B swizzled rows), 3-stage cp.async ring,
// ONE __syncthreads per k-iter. 2 CTAs/SM.
// MODE 0: scatter to g_q16 (x0.125) / g_k16 / g_vT16 (transposed).
// MODE 1: fp32 out + bias.
// ---------------------------------------------------------------------------
#define TILE_B  (128*128)          // bytes per operand tile
#define STAGE_B (2*TILE_B)         // 32768 B
#define GSM     (3*STAGE_B)        // 98304 B
#define KT16    (GK/64)            // 12

template<int MODE>
__global__ void __launch_bounds__(128,2) gemm_k(
    const __half* __restrict__ Bw, const float* __restrict__ bias,
    float* __restrict__ Cout)
{
    extern __shared__ char smc[];
    const unsigned smb = (unsigned)__cvta_generic_to_shared(smc);
    const __half* A = (MODE == 0) ? g_query16 : g_ctx16;

    const int t = threadIdx.x;
    const int lane = t & 31, wid = t >> 5;
    const int group = lane >> 2, tig = lane & 3;
    const int wm = wid >> 1, wn = wid & 1;
    const int m0 = blockIdx.y * 128, n0 = blockIdx.x * 128;
    const int l16 = lane & 15, lh = lane >> 4;

    // loader: 1024 16B-segs per operand, 8 per thread (precomputed bases)
    const __half* aP[8]; const __half* bP[8]; unsigned so[8];
#pragma unroll
    for (int j = 0; j < 8; j++) {
        const int s = t + j * 128;
        const int row = s >> 3, c16 = s & 7;
        so[j] = swz((unsigned)(row * 128 + c16 * 16));
        aP[j] = A  + (size_t)(m0 + row) * GK + c16 * 8;
        bP[j] = Bw + (size_t)(n0 + row) * GK + c16 * 8;
    }
    auto load_stage = [&](int kt, int st){
        const unsigned ab = smb + (unsigned)st * STAGE_B;
        const unsigned bb = ab + TILE_B;
#pragma unroll
        for (int j = 0; j < 8; j++) {
            cpasync16(ab + so[j], aP[j] + kt * 64);
            cpasync16(bb + so[j], bP[j] + kt * 64);
        }
        cp_commit();
    };

    float acc[4][8][4];
#pragma unroll
    for (int mi = 0; mi < 4; mi++)
#pragma unroll
        for (int ni = 0; ni < 8; ni++)
#pragma unroll
            for (int v = 0; v < 4; v++) acc[mi][ni][v] = 0.f;

    load_stage(0, 0);
    load_stage(1, 1);

#pragma unroll 1
    for (int kt = 0; kt < KT16; kt++) {
        if (kt + 1 < KT16) cp_wait1(); else cp_wait0();
        __syncthreads();
        if (kt + 2 < KT16) load_stage(kt + 2, (kt + 2) % 3);

        const unsigned ab = smb + (unsigned)(kt % 3) * STAGE_B;
        const unsigned bb = ab + TILE_B;
#pragma unroll
        for (int ks = 0; ks < 4; ks++) {
            unsigned af[4][4], br[4][4];
#pragma unroll
            for (int mi = 0; mi < 4; mi++)
                ldsm4(af[mi], ab + swz((unsigned)((wm*64 + mi*16 + l16) * 128 + lh*16 + ks*32)));
#pragma unroll
            for (int p = 0; p < 4; p++)
                ldsm4(br[p], bb + swz((unsigned)((wn*64 + p*16 + l16) * 128 + lh*16 + ks*32)));
#pragma unroll
            for (int mi = 0; mi < 4; mi++)
#pragma unroll
                for (int p = 0; p < 4; p++) {
                    unsigned b0[2] = { br[p][0], br[p][2] };
                    unsigned b1[2] = { br[p][1], br[p][3] };
                    mma16(acc[mi][2*p],   af[mi], b0);
                    mma16(acc[mi][2*p+1], af[mi], b1);
                }
        }
    }

    // epilogue
    float bv0[8], bv1[8];
#pragma unroll
    for (int ni = 0; ni < 8; ni++) {
        const int c = n0 + wn * 64 + ni * 8 + 2 * tig;
        bv0[ni] = bias[c]; bv1[ni] = bias[c + 1];
    }

    if (MODE == 0) {
        const int which = blockIdx.x / 6;   // 0=q 1=k 2=v
        const float qs = (which == 0) ? 0.125f : 1.0f;
#pragma unroll
        for (int mi = 0; mi < 4; mi++)
#pragma unroll
            for (int rr = 0; rr < 2; rr++) {
                const int r  = m0 + wm * 64 + mi * 16 + group + rr * 8;
                const int bi = r >> 10, nidx = r & 1023;
#pragma unroll
                for (int ni = 0; ni < 8; ni++) {
                    const int c = n0 + wn * 64 + ni * 8 + 2 * tig;
                    const int e = c - which * 768;
                    const int h = e >> 6, d = e & 63;
                    const float vx = (acc[mi][ni][rr*2+0] + bv0[ni]) * qs;
                    const float vy = (acc[mi][ni][rr*2+1] + bv1[ni]) * qs;
                    if (which == 2) {
                        const size_t base = (((size_t)bi * HH + h) * HD + d) * NN + nidx;
                        g_vT16[base]      = __float2half_rn(vx);
                        g_vT16[base + NN] = __float2half_rn(vy);
                    } else {
                        __half* dst = (which == 0 ? g_q16 : g_k16)
                                    + ((((size_t)bi * HH + h) * NN + nidx) * HD + d);
                        *(__half2*)dst = __floats2half2_rn(vx, vy);
                    }
                }
            }
    } else {
#pragma unroll
        for (int mi = 0; mi < 4; mi++)
#pragma unroll
            for (int rr = 0; rr < 2; rr++) {
                const int r = m0 + wm * 64 + mi * 16 + group + rr * 8;
#pragma unroll
                for (int ni = 0; ni < 8; ni++) {
                    const int c = n0 + wn * 64 + ni * 8 + 2 * tig;
                    float2 val;
                    val.x = acc[mi][ni][rr*2+0] + bv0[ni];
                    val.y = acc[mi][ni][rr*2+1] + bv1[ni];
                    *(float2*)&Cout[(size_t)r * EE + c] = val;
                }
            }
    }
}

// ---------------------------------------------------------------------------
// Flash attention fp16: 128 thr (4 warps x 32 q-rows), q-tile 128, kv-tile 64.
// Qs[128][64h] (pre-scaled), Ks/VTs double-buffered cp.async, Ps[128][64h].
// ONE __syncthreads per kv-iter (load of next tile issued after it).
// ---------------------------------------------------------------------------
#define ATT_Q   0
#define ATT_K0  16384
#define ATT_V0  32768
#define ATT_P   49152
#define ATT_SM  65536

__global__ void __launch_bounds__(128,2) attn_k()
{
    extern __shared__ char smc[];
    const unsigned smb = (unsigned)__cvta_generic_to_shared(smc);

    const int t = threadIdx.x, lane = t & 31, wid = t >> 5;
    const int group = lane >> 2, tig = lane & 3;
    const int l16 = lane & 15, lh = lane >> 4;
    const int bh = blockIdx.y, qt = blockIdx.x;

    // K/V loader: 512 16B-segs per operand, 4 per thread
    const __half* kP[4]; const __half* vP[4]; unsigned kso[4];
#pragma unroll
    for (int j = 0; j < 4; j++) {
        const int s = t + j * 128;
        const int row = s >> 3, c16 = s & 7;
        kso[j] = swz((unsigned)(row * 128 + c16 * 16));
        kP[j] = g_k16  + ((size_t)bh * NN + row) * HD + c16 * 8;
        vP[j] = g_vT16 + ((size_t)bh * HD + row) * NN + c16 * 8;
    }
    auto load_kv = [&](int kt, int st){
        const unsigned kb = smb + ATT_K0 + (unsigned)st * 8192u;
        const unsigned vb = smb + ATT_V0 + (unsigned)st * 8192u;
#pragma unroll
        for (int j = 0; j < 4; j++) {
            cpasync16(kb + kso[j], kP[j] + (size_t)(kt * 64) * HD);  // +64 rows
            cpasync16(vb + kso[j], vP[j] + kt * 64);                 // +64 cols
        }
        cp_commit();
    };

    {   // stage Q (1024 segs, 8/thread) + K/V tile 0 in ONE group
        const __half* gq = g_q16 + ((size_t)bh * NN + qt * 128) * HD;
#pragma unroll
        for (int j = 0; j < 8; j++) {
            const int s = t + j * 128;
            const int row = s >> 3, c16 = s & 7;
            cpasync16(smb + ATT_Q + swz((unsigned)(row * 128 + c16 * 16)),
                      gq + (size_t)row * HD + c16 * 8);
        }
        load_kv(0, 0);   // commits the combined group
    }

    float oc[2][8][4];
#pragma unroll
    for (int mi = 0; mi < 2; mi++)
#pragma unroll
        for (int ni = 0; ni < 8; ni++)
#pragma unroll
            for (int v = 0; v < 4; v++) oc[mi][ni][v] = 0.f;
    float mprev[2][2] = {{-1e30f,-1e30f},{-1e30f,-1e30f}};
    float lsum[2][2]  = {{0.f,0.f},{0.f,0.f}};

#pragma unroll 1
    for (int kt = 0; kt < 16; kt++) {
        cp_wait0();
        __syncthreads();            // all copies visible; all warps done with prev bufs
        if (kt + 1 < 16) load_kv(kt + 1, (kt + 1) & 1);

        const unsigned kb = smb + ATT_K0 + (unsigned)(kt & 1) * 8192u;
        const unsigned vb = smb + ATT_V0 + (unsigned)(kt & 1) * 8192u;

        // S = Q K^T : per warp 32 q-rows x 64 keys (k = d, 4 steps of 16)
        float sc[2][8][4];
#pragma unroll
        for (int mi = 0; mi < 2; mi++)
#pragma unroll
            for (int ni = 0; ni < 8; ni++)
#pragma unroll
                for (int v = 0; v < 4; v++) sc[mi][ni][v] = 0.f;
#pragma unroll
        for (int ks = 0; ks < 4; ks++) {
            unsigned a[2][4];
#pragma unroll
            for (int mi = 0; mi < 2; mi++)
                ldsm4(a[mi], smb + ATT_Q + swz((unsigned)((wid*32 + mi*16 + l16) * 128 + lh*16 + ks*32)));
#pragma unroll
            for (int p = 0; p < 4; p++) {
                unsigned br[4];
                ldsm4(br, kb + swz((unsigned)((p*16 + l16) * 128 + lh*16 + ks*32)));
                unsigned b0[2] = { br[0], br[2] };
                unsigned b1[2] = { br[1], br[3] };
#pragma unroll
                for (int mi = 0; mi < 2; mi++) {
                    mma16(sc[mi][2*p],   a[mi], b0);
                    mma16(sc[mi][2*p+1], a[mi], b1);
                }
            }
        }

        // online softmax (4 row-stats per thread; stats across lane quad)
#pragma unroll
        for (int mi = 0; mi < 2; mi++)
#pragma unroll
            for (int rr = 0; rr < 2; rr++) {
                float tm = -1e30f;
#pragma unroll
                for (int ni = 0; ni < 8; ni++)
                    tm = fmaxf(tm, fmaxf(sc[mi][ni][rr*2], sc[mi][ni][rr*2+1]));
                tm = fmaxf(tm, __shfl_xor_sync(0xffffffffu, tm, 1));
                tm = fmaxf(tm, __shfl_xor_sync(0xffffffffu, tm, 2));
                const float mnew = fmaxf(mprev[mi][rr], tm);
                const float corr = __expf(mprev[mi][rr] - mnew);
                mprev[mi][rr] = mnew;
                float rs = 0.f;
#pragma unroll
                for (int ni = 0; ni < 8; ni++) {
                    const float p0 = __expf(sc[mi][ni][rr*2]   - mnew);
                    const float p1 = __expf(sc[mi][ni][rr*2+1] - mnew);
                    sc[mi][ni][rr*2] = p0; sc[mi][ni][rr*2+1] = p1;
                    rs += p0 + p1;
                }
                rs += __shfl_xor_sync(0xffffffffu, rs, 1);
                rs += __shfl_xor_sync(0xffffffffu, rs, 2);
                lsum[mi][rr] = lsum[mi][rr] * corr + rs;
#pragma unroll
                for (int ni = 0; ni < 8; ni++) {
                    oc[mi][ni][rr*2]   *= corr;
                    oc[mi][ni][rr*2+1] *= corr;
                }
            }

        // stage P as half2 [m][key] (own warp's 32 rows only)
#pragma unroll
        for (int mi = 0; mi < 2; mi++) {
            const int row0 = wid * 32 + mi * 16 + group;
#pragma unroll
            for (int ni = 0; ni < 8; ni++) {
                const int col = ni * 8 + 2 * tig;
                __half2 v0 = __floats2half2_rn(sc[mi][ni][0], sc[mi][ni][1]);
                __half2 v1 = __floats2half2_rn(sc[mi][ni][2], sc[mi][ni][3]);
                *(__half2*)(smc + ATT_P + swz((unsigned)( row0      * 128 + col * 2))) = v0;
                *(__half2*)(smc + ATT_P + swz((unsigned)((row0 + 8) * 128 + col * 2))) = v1;
            }
        }
        __syncwarp();

        // O += P V  (A = P rows, B = V^T rows d; k = keys, 4 steps of 16)
#pragma unroll
        for (int ks = 0; ks < 4; ks++) {
            unsigned a[2][4];
#pragma unroll
            for (int mi = 0; mi < 2; mi++)
                ldsm4(a[mi], smb + ATT_P + swz((unsigned)((wid*32 + mi*16 + l16) * 128 + lh*16 + ks*32)));
#pragma unroll
            for (int p = 0; p < 4; p++) {
                unsigned br[4];
                ldsm4(br, vb + swz((unsigned)((p*16 + l16) * 128 + lh*16 + ks*32)));
                unsigned b0[2] = { br[0], br[2] };
                unsigned b1[2] = { br[1], br[3] };
#pragma unroll
                for (int mi = 0; mi < 2; mi++) {
                    mma16(oc[mi][2*p],   a[mi], b0);
                    mma16(oc[mi][2*p+1], a[mi], b1);
                }
            }
        }
    }

    // normalize + write ctx16 [8192,768] at col h*64
    const int bi = bh / HH, h = bh % HH;
#pragma unroll
    for (int mi = 0; mi < 2; mi++)
#pragma unroll
        for (int rr = 0; rr < 2; rr++) {
            const float inv = 1.0f / lsum[mi][rr];
            const int qrow = qt * 128 + wid * 32 + mi * 16 + group + rr * 8;
            const size_t rowoff = ((size_t)bi * NN + qrow) * EE + h * HD;
#pragma unroll
            for (int ni = 0; ni < 8; ni++) {
                __half2 v = __floats2half2_rn(oc[mi][ni][rr*2] * inv, oc[mi][ni][rr*2+1] * inv);
                *(__half2*)&g_ctx16[rowoff + ni * 8 + 2 * tig] = v;
            }
        }
}

// ---------------------------------------------------------------------------
extern "C" void kernel_launch(void* const* d_in, const int* in_sizes, int n_in,
                              void* d_out, int out_size)
{
    const float* query = (const float*)d_in[0];
    const float* qkv_w = (const float*)d_in[1];
    const float* qkv_b = (const float*)d_in[2];
    const float* out_w = (const float*)d_in[3];
    const float* out_b = (const float*)d_in[4];
    float* out = (float*)d_out;

    cudaFuncSetAttribute(gemm_k<0>, cudaFuncAttributeMaxDynamicSharedMemorySize, GSM);
    cudaFuncSetAttribute(gemm_k<1>, cudaFuncAttributeMaxDynamicSharedMemorySize, GSM);
    cudaFuncSetAttribute(attn_k,    cudaFuncAttributeMaxDynamicSharedMemorySize, ATT_SM);

    static __half *w1p = nullptr, *w2p = nullptr;
    if (!w1p) { cudaGetSymbolAddress((void**)&w1p, g_qkvw16);
                cudaGetSymbolAddress((void**)&w2p, g_outw16); }

    cvt_k<<<1024, 256>>>(query, qkv_w, out_w);
    gemm_k<0><<<dim3(18, 64), 128, GSM>>>(w1p, qkv_b, nullptr);
    attn_k<<<dim3(8, 96), 128, ATT_SM>>>();
    gemm_k<1><<<dim3(6, 64), 128, GSM>>>(w2p, out_b, out);
}

// round 14
// speedup vs baseline: 2.6982x; 1.0040x over previous
#include <cuda_runtime.h>
#include <cuda_fp16.h>
#include <math.h>

#define BB 8
#define NN 1024
#define EE 768
#define HH 12
#define HD 64
#define GK 768

// fp16 scratch (device globals: allocation-free per harness rules)
__device__ __half g_query16[(size_t)BB*NN*EE];   // [8192,768]
__device__ __half g_qkvw16[(size_t)3*EE*EE];     // [2304,768]
__device__ __half g_outw16[(size_t)EE*EE];       // [768,768]
__device__ __half g_q16[(size_t)BB*HH*NN*HD];    // [B,H,N,64]  (pre-scaled 1/8)
__device__ __half g_k16[(size_t)BB*HH*NN*HD];    // [B,H,N,64]
__device__ __half g_vT16[(size_t)BB*HH*HD*NN];   // [B,H,64,N]  (transposed!)
__device__ __half g_ctx16[(size_t)BB*NN*EE];     // [8192,768]

__device__ __forceinline__ void mma16(float* c, const unsigned* a, const unsigned* b){
    asm volatile("mma.sync.aligned.m16n8k16.row.col.f32.f16.f16.f32 "
        "{%0,%1,%2,%3}, {%4,%5,%6,%7}, {%8,%9}, {%0,%1,%2,%3};\n"
        : "+f"(c[0]),"+f"(c[1]),"+f"(c[2]),"+f"(c[3])
        : "r"(a[0]),"r"(a[1]),"r"(a[2]),"r"(a[3]), "r"(b[0]),"r"(b[1]));
}
__device__ __forceinline__ void cpasync16(unsigned saddr, const void* gptr){
    asm volatile("cp.async.cg.shared.global [%0], [%1], 16;\n" :: "r"(saddr), "l"(gptr) : "memory");
}
__device__ __forceinline__ void cp_commit(){ asm volatile("cp.async.commit_group;\n" ::: "memory"); }
__device__ __forceinline__ void cp_wait0(){ asm volatile("cp.async.wait_group 0;\n" ::: "memory"); }
__device__ __forceinline__ void cp_wait1(){ asm volatile("cp.async.wait_group 1;\n" ::: "memory"); }
__device__ __forceinline__ void ldsm4(unsigned* r, unsigned saddr){
    asm volatile("ldmatrix.sync.aligned.m8n8.x4.shared.b16 {%0,%1,%2,%3}, [%4];\n"
        : "=r"(r[0]),"=r"(r[1]),"=r"(r[2]),"=r"(r[3]) : "r"(saddr));
}
__device__ __forceinline__ unsigned swz(unsigned x){ return x ^ ((x >> 3) & 0x70); }

// ---------------------------------------------------------------------------
// fp32 -> fp16 pre-convert (query, qkv_w, out_w)
// ---------------------------------------------------------------------------
__global__ void cvt_k(const float* __restrict__ q, const float* __restrict__ w1,
                      const float* __restrict__ w2)
{
    const int NQ = (BB*NN*EE)/4, NW1 = (3*EE*EE)/4, NW2 = (EE*EE)/4;
    const int stride = gridDim.x * blockDim.x;
    int i = blockIdx.x * blockDim.x + threadIdx.x;
    for (int j = i; j < NQ; j += stride) {
        float4 v = ((const float4*)q)[j];
        __half2 h0 = __floats2half2_rn(v.x, v.y), h1 = __floats2half2_rn(v.z, v.w);
        ((uint2*)g_query16)[j] = make_uint2(*(unsigned*)&h0, *(unsigned*)&h1);
    }
    for (int j = i; j < NW1; j += stride) {
        float4 v = ((const float4*)w1)[j];
        __half2 h0 = __floats2half2_rn(v.x, v.y), h1 = __floats2half2_rn(v.z, v.w);
        ((uint2*)g_qkvw16)[j] = make_uint2(*(unsigned*)&h0, *(unsigned*)&h1);
    }
    for (int j = i; j < NW2; j += stride) {
        float4 v = ((const float4*)w2)[j];
        __half2 h0 = __floats2half2_rn(v.x, v.y), h1 = __floats2half2_rn(v.z, v.w);
        ((uint2*)g_outw16)[j] = make_uint2(*(unsigned*)&h0, *(unsigned*)&h1);
    }
}

// ---------------------------------------------------------------------------
// fp16 NT GEMM: C[M,Ncols] = A[M,768] @ W[Ncols,768]^T + bias
// CTA 128x128, 128 thr (4 warps 2x2), warp 64x64, mma m16n8k16 f16->f32.
// k-chunks of 64 halves (128B swizzled rows), 3-stage cp.async ring,
// ONE __syncthreads per k-iter. 2 CTAs/SM.
// MODE 0: scatter to g_q16 (x0.125) / g_k16 / g_vT16 (transposed).
// MODE 1: fp32 out + bias.
// ---------------------------------------------------------------------------
#define TILE_B  (128*128)          // bytes per operand tile
#define STAGE_B (2*TILE_B)         // 32768 B
#define GSM     (3*STAGE_B)        // 98304 B
#define KT16    (GK/64)            // 12

template<int MODE>
__global__ void __launch_bounds__(128,2) gemm_k(
    const __half* __restrict__ Bw, const float* __restrict__ bias,
    float* __restrict__ Cout)
{
    extern __shared__ char smc[];
    const unsigned smb = (unsigned)__cvta_generic_to_shared(smc);
    const __half* A = (MODE == 0) ? g_query16 : g_ctx16;

    const int t = threadIdx.x;
    const int lane = t & 31, wid = t >> 5;
    const int group = lane >> 2, tig = lane & 3;
    const int wm = wid >> 1, wn = wid & 1;
    const int m0 = blockIdx.y * 128, n0 = blockIdx.x * 128;
    const int l16 = lane & 15, lh = lane >> 4;

    // loader: 1024 16B-segs per operand, 8 per thread (precomputed bases)
    const __half* aP[8]; const __half* bP[8]; unsigned so[8];
#pragma unroll
    for (int j = 0; j < 8; j++) {
        const int s = t + j * 128;
        const int row = s >> 3, c16 = s & 7;
        so[j] = swz((unsigned)(row * 128 + c16 * 16));
        aP[j] = A  + (size_t)(m0 + row) * GK + c16 * 8;
        bP[j] = Bw + (size_t)(n0 + row) * GK + c16 * 8;
    }
    auto load_stage = [&](int kt, int st){
        const unsigned ab = smb + (unsigned)st * STAGE_B;
        const unsigned bb = ab + TILE_B;
#pragma unroll
        for (int j = 0; j < 8; j++) {
            cpasync16(ab + so[j], aP[j] + kt * 64);
            cpasync16(bb + so[j], bP[j] + kt * 64);
        }
        cp_commit();
    };

    float acc[4][8][4];
#pragma unroll
    for (int mi = 0; mi < 4; mi++)
#pragma unroll
        for (int ni = 0; ni < 8; ni++)
#pragma unroll
            for (int v = 0; v < 4; v++) acc[mi][ni][v] = 0.f;

    load_stage(0, 0);
    load_stage(1, 1);

#pragma unroll 1
    for (int kt = 0; kt < KT16; kt++) {
        if (kt + 1 < KT16) cp_wait1(); else cp_wait0();
        __syncthreads();
        if (kt + 2 < KT16) load_stage(kt + 2, (kt + 2) % 3);

        const unsigned ab = smb + (unsigned)(kt % 3) * STAGE_B;
        const unsigned bb = ab + TILE_B;
#pragma unroll
        for (int ks = 0; ks < 4; ks++) {
            unsigned af[4][4], br[4][4];
#pragma unroll
            for (int mi = 0; mi < 4; mi++)
                ldsm4(af[mi], ab + swz((unsigned)((wm*64 + mi*16 + l16) * 128 + lh*16 + ks*32)));
#pragma unroll
            for (int p = 0; p < 4; p++)
                ldsm4(br[p], bb + swz((unsigned)((wn*64 + p*16 + l16) * 128 + lh*16 + ks*32)));
#pragma unroll
            for (int mi = 0; mi < 4; mi++)
#pragma unroll
                for (int p = 0; p < 4; p++) {
                    unsigned b0[2] = { br[p][0], br[p][2] };
                    unsigned b1[2] = { br[p][1], br[p][3] };
                    mma16(acc[mi][2*p],   af[mi], b0);
                    mma16(acc[mi][2*p+1], af[mi], b1);
                }
        }
    }

    // epilogue
    float bv0[8], bv1[8];
#pragma unroll
    for (int ni = 0; ni < 8; ni++) {
        const int c = n0 + wn * 64 + ni * 8 + 2 * tig;
        bv0[ni] = bias[c]; bv1[ni] = bias[c + 1];
    }

    if (MODE == 0) {
        const int which = blockIdx.x / 6;   // 0=q 1=k 2=v
        const float qs = (which == 0) ? 0.125f : 1.0f;
#pragma unroll
        for (int mi = 0; mi < 4; mi++)
#pragma unroll
            for (int rr = 0; rr < 2; rr++) {
                const int r  = m0 + wm * 64 + mi * 16 + group + rr * 8;
                const int bi = r >> 10, nidx = r & 1023;
#pragma unroll
                for (int ni = 0; ni < 8; ni++) {
                    const int c = n0 + wn * 64 + ni * 8 + 2 * tig;
                    const int e = c - which * 768;
                    const int h = e >> 6, d = e & 63;
                    const float vx = (acc[mi][ni][rr*2+0] + bv0[ni]) * qs;
                    const float vy = (acc[mi][ni][rr*2+1] + bv1[ni]) * qs;
                    if (which == 2) {
                        const size_t base = (((size_t)bi * HH + h) * HD + d) * NN + nidx;
                        g_vT16[base]      = __float2half_rn(vx);
                        g_vT16[base + NN] = __float2half_rn(vy);
                    } else {
                        __half* dst = (which == 0 ? g_q16 : g_k16)
                                    + ((((size_t)bi * HH + h) * NN + nidx) * HD + d);
                        *(__half2*)dst = __floats2half2_rn(vx, vy);
                    }
                }
            }
    } else {
#pragma unroll
        for (int mi = 0; mi < 4; mi++)
#pragma unroll
            for (int rr = 0; rr < 2; rr++) {
                const int r = m0 + wm * 64 + mi * 16 + group + rr * 8;
#pragma unroll
                for (int ni = 0; ni < 8; ni++) {
                    const int c = n0 + wn * 64 + ni * 8 + 2 * tig;
                    float2 val;
                    val.x = acc[mi][ni][rr*2+0] + bv0[ni];
                    val.y = acc[mi][ni][rr*2+1] + bv1[ni];
                    *(float2*)&Cout[(size_t)r * EE + c] = val;
                }
            }
    }
}

// ---------------------------------------------------------------------------
// Flash attention fp16: 128 thr (4 warps x 32 q-rows), q-tile 128, kv-tile 64.
// Qs[128][64h] (pre-scaled), Ks/VTs double-buffered cp.async, Ps[128][64h].
// ONE __syncthreads per kv-iter (load of next tile issued after it).
// ---------------------------------------------------------------------------
#define ATT_Q   0
#define ATT_K0  16384
#define ATT_V0  32768
#define ATT_P   49152
#define ATT_SM  65536

__global__ void __launch_bounds__(128,2) attn_k()
{
    extern __shared__ char smc[];
    const unsigned smb = (unsigned)__cvta_generic_to_shared(smc);

    const int t = threadIdx.x, lane = t & 31, wid = t >> 5;
    const int group = lane >> 2, tig = lane & 3;
    const int l16 = lane & 15, lh = lane >> 4;
    const int bh = blockIdx.y, qt = blockIdx.x;

    // K/V loader: 512 16B-segs per operand, 4 per thread
    const __half* kP[4]; const __half* vP[4]; unsigned kso[4];
#pragma unroll
    for (int j = 0; j < 4; j++) {
        const int s = t + j * 128;
        const int row = s >> 3, c16 = s & 7;
        kso[j] = swz((unsigned)(row * 128 + c16 * 16));
        kP[j] = g_k16  + ((size_t)bh * NN + row) * HD + c16 * 8;
        vP[j] = g_vT16 + ((size_t)bh * HD + row) * NN + c16 * 8;
    }
    auto load_kv = [&](int kt, int st){
        const unsigned kb = smb + ATT_K0 + (unsigned)st * 8192u;
        const unsigned vb = smb + ATT_V0 + (unsigned)st * 8192u;
#pragma unroll
        for (int j = 0; j < 4; j++) {
            cpasync16(kb + kso[j], kP[j] + (size_t)(kt * 64) * HD);  // +64 rows
            cpasync16(vb + kso[j], vP[j] + kt * 64);                 // +64 cols
        }
        cp_commit();
    };

    {   // stage Q (1024 segs, 8/thread) + K/V tile 0 in ONE group
        const __half* gq = g_q16 + ((size_t)bh * NN + qt * 128) * HD;
#pragma unroll
        for (int j = 0; j < 8; j++) {
            const int s = t + j * 128;
            const int row = s >> 3, c16 = s & 7;
            cpasync16(smb + ATT_Q + swz((unsigned)(row * 128 + c16 * 16)),
                      gq + (size_t)row * HD + c16 * 8);
        }
        load_kv(0, 0);   // commits the combined group
    }

    float oc[2][8][4];
#pragma unroll
    for (int mi = 0; mi < 2; mi++)
#pragma unroll
        for (int ni = 0; ni < 8; ni++)
#pragma unroll
            for (int v = 0; v < 4; v++) oc[mi][ni][v] = 0.f;
    float mprev[2][2] = {{-1e30f,-1e30f},{-1e30f,-1e30f}};
    float lsum[2][2]  = {{0.f,0.f},{0.f,0.f}};

#pragma unroll 1
    for (int kt = 0; kt < 16; kt++) {
        cp_wait0();
        __syncthreads();            // all copies visible; all warps done with prev bufs
        if (kt + 1 < 16) load_kv(kt + 1, (kt + 1) & 1);

        const unsigned kb = smb + ATT_K0 + (unsigned)(kt & 1) * 8192u;
        const unsigned vb = smb + ATT_V0 + (unsigned)(kt & 1) * 8192u;

        // S = Q K^T : per warp 32 q-rows x 64 keys (k = d, 4 steps of 16)
        float sc[2][8][4];
#pragma unroll
        for (int mi = 0; mi < 2; mi++)
#pragma unroll
            for (int ni = 0; ni < 8; ni++)
#pragma unroll
                for (int v = 0; v < 4; v++) sc[mi][ni][v] = 0.f;
#pragma unroll
        for (int ks = 0; ks < 4; ks++) {
            unsigned a[2][4];
#pragma unroll
            for (int mi = 0; mi < 2; mi++)
                ldsm4(a[mi], smb + ATT_Q + swz((unsigned)((wid*32 + mi*16 + l16) * 128 + lh*16 + ks*32)));
#pragma unroll
            for (int p = 0; p < 4; p++) {
                unsigned br[4];
                ldsm4(br, kb + swz((unsigned)((p*16 + l16) * 128 + lh*16 + ks*32)));
                unsigned b0[2] = { br[0], br[2] };
                unsigned b1[2] = { br[1], br[3] };
#pragma unroll
                for (int mi = 0; mi < 2; mi++) {
                    mma16(sc[mi][2*p],   a[mi], b0);
                    mma16(sc[mi][2*p+1], a[mi], b1);
                }
            }
        }

        // online softmax (4 row-stats per thread; stats across lane quad)
#pragma unroll
        for (int mi = 0; mi < 2; mi++)
#pragma unroll
            for (int rr = 0; rr < 2; rr++) {
                float tm = -1e30f;
#pragma unroll
                for (int ni = 0; ni < 8; ni++)
                    tm = fmaxf(tm, fmaxf(sc[mi][ni][rr*2], sc[mi][ni][rr*2+1]));
                tm = fmaxf(tm, __shfl_xor_sync(0xffffffffu, tm, 1));
                tm = fmaxf(tm, __shfl_xor_sync(0xffffffffu, tm, 2));
                const float mnew = fmaxf(mprev[mi][rr], tm);
                const float corr = __expf(mprev[mi][rr] - mnew);
                mprev[mi][rr] = mnew;
                float rs = 0.f;
#pragma unroll
                for (int ni = 0; ni < 8; ni++) {
                    const float p0 = __expf(sc[mi][ni][rr*2]   - mnew);
                    const float p1 = __expf(sc[mi][ni][rr*2+1] - mnew);
                    sc[mi][ni][rr*2] = p0; sc[mi][ni][rr*2+1] = p1;
                    rs += p0 + p1;
                }
                rs += __shfl_xor_sync(0xffffffffu, rs, 1);
                rs += __shfl_xor_sync(0xffffffffu, rs, 2);
                lsum[mi][rr] = lsum[mi][rr] * corr + rs;
#pragma unroll
                for (int ni = 0; ni < 8; ni++) {
                    oc[mi][ni][rr*2]   *= corr;
                    oc[mi][ni][rr*2+1] *= corr;
                }
            }

        // stage P as half2 [m][key] (own warp's 32 rows only)
#pragma unroll
        for (int mi = 0; mi < 2; mi++) {
            const int row0 = wid * 32 + mi * 16 + group;
#pragma unroll
            for (int ni = 0; ni < 8; ni++) {
                const int col = ni * 8 + 2 * tig;
                __half2 v0 = __floats2half2_rn(sc[mi][ni][0], sc[mi][ni][1]);
                __half2 v1 = __floats2half2_rn(sc[mi][ni][2], sc[mi][ni][3]);
                *(__half2*)(smc + ATT_P + swz((unsigned)( row0      * 128 + col * 2))) = v0;
                *(__half2*)(smc + ATT_P + swz((unsigned)((row0 + 8) * 128 + col * 2))) = v1;
            }
        }
        __syncwarp();

        // O += P V  (A = P rows, B = V^T rows d; k = keys, 4 steps of 16)
#pragma unroll
        for (int ks = 0; ks < 4; ks++) {
            unsigned a[2][4];
#pragma unroll
            for (int mi = 0; mi < 2; mi++)
                ldsm4(a[mi], smb + ATT_P + swz((unsigned)((wid*32 + mi*16 + l16) * 128 + lh*16 + ks*32)));
#pragma unroll
            for (int p = 0; p < 4; p++) {
                unsigned br[4];
                ldsm4(br, vb + swz((unsigned)((p*16 + l16) * 128 + lh*16 + ks*32)));
                unsigned b0[2] = { br[0], br[2] };
                unsigned b1[2] = { br[1], br[3] };
#pragma unroll
                for (int mi = 0; mi < 2; mi++) {
                    mma16(oc[mi][2*p],   a[mi], b0);
                    mma16(oc[mi][2*p+1], a[mi], b1);
                }
            }
        }
    }

    // normalize + write ctx16 [8192,768] at col h*64
    const int bi = bh / HH, h = bh % HH;
#pragma unroll
    for (int mi = 0; mi < 2; mi++)
#pragma unroll
        for (int rr = 0; rr < 2; rr++) {
            const float inv = 1.0f / lsum[mi][rr];
            const int qrow = qt * 128 + wid * 32 + mi * 16 + group + rr * 8;
            const size_t rowoff = ((size_t)bi * NN + qrow) * EE + h * HD;
#pragma unroll
            for (int ni = 0; ni < 8; ni++) {
                __half2 v = __floats2half2_rn(oc[mi][ni][rr*2] * inv, oc[mi][ni][rr*2+1] * inv);
                *(__half2*)&g_ctx16[rowoff + ni * 8 + 2 * tig] = v;
            }
        }
}

// ---------------------------------------------------------------------------
extern "C" void kernel_launch(void* const* d_in, const int* in_sizes, int n_in,
                              void* d_out, int out_size)
{
    const float* query = (const float*)d_in[0];
    const float* qkv_w = (const float*)d_in[1];
    const float* qkv_b = (const float*)d_in[2];
    const float* out_w = (const float*)d_in[3];
    const float* out_b = (const float*)d_in[4];
    float* out = (float*)d_out;

    cudaFuncSetAttribute(gemm_k<0>, cudaFuncAttributeMaxDynamicSharedMemorySize, GSM);
    cudaFuncSetAttribute(gemm_k<1>, cudaFuncAttributeMaxDynamicSharedMemorySize, GSM);
    cudaFuncSetAttribute(attn_k,    cudaFuncAttributeMaxDynamicSharedMemorySize, ATT_SM);

    static __half *w1p = nullptr, *w2p = nullptr;
    if (!w1p) { cudaGetSymbolAddress((void**)&w1p, g_qkvw16);
                cudaGetSymbolAddress((void**)&w2p, g_outw16); }

    cvt_k<<<1024, 256>>>(query, qkv_w, out_w);
    gemm_k<0><<<dim3(18, 64), 128, GSM>>>(w1p, qkv_b, nullptr);
    attn_k<<<dim3(8, 96), 128, ATT_SM>>>();
    gemm_k<1><<<dim3(6, 64), 128, GSM>>>(w2p, out_b, out);
}